// round 1
// baseline (speedup 1.0000x reference)
#include <cuda_runtime.h>
#include <math.h>

typedef unsigned long long u64;

#define NB      8
#define T0      8192
#define HID     128
#define TARGET  6146
#define NLAY    20

// ---------------- scratch (device globals; no allocation) ----------------
__device__ float g_res0[(size_t)NB * T0 * HID];
__device__ float g_res1[(size_t)NB * T0 * HID];
__device__ float g_skip[(size_t)NB * TARGET * HID];
__device__ float g_mid [(size_t)NB * TARGET * 512];

// ---------------- packed f32x2 helpers (FFMA2 path) ----------------
__device__ __forceinline__ u64 pk2s(float w) {
    u64 r; asm("mov.b64 %0, {%1, %1};" : "=l"(r) : "f"(w)); return r;
}
__device__ __forceinline__ float2 upk(u64 v) {
    float2 f; asm("mov.b64 {%0, %1}, %2;" : "=f"(f.x), "=f"(f.y) : "l"(v)); return f;
}
__device__ __forceinline__ u64 f2fma(u64 a, u64 b, u64 c) {
    u64 d; asm("fma.rn.f32x2 %0, %1, %2, %3;" : "=l"(d) : "l"(a), "l"(b), "l"(c)); return d;
}

// smem sizes (bytes)
#define LAYER_SMEM ((2*128*68 + 4*128*65) * 4)      // 202752
#define IN_SMEM    ((256*68 + 128*257) * 4)         // 201216
#define H1_SMEM    ((128*68 + 128*129) * 4)         // 100864
#define H2_SMEM    ((128*68 + 256*129) * 4)         // 166912

// =====================================================================
// Input GEMM: res0[b][t][c] = Wi[c,:] . inputs[b,:,t] + bi[c]
// =====================================================================
__global__ __launch_bounds__(512, 1) void in_kernel(
    const float* __restrict__ inp, const float* __restrict__ Wi,
    const float* __restrict__ bi)
{
    extern __shared__ float sm[];
    float* hs = sm;             // [256][68]
    float* ws = sm + 256*68;    // [128][257]
    const int tid = threadIdx.x;
    const int b = blockIdx.y;
    const int t0 = blockIdx.x * 64;

    const float* ib = inp + (size_t)b * 256 * T0;
    for (int e = tid; e < 256*16; e += 512) {
        int i = e >> 4, j4 = e & 15;
        float4 v = *(const float4*)(ib + (size_t)i * T0 + t0 + j4*4);
        *(float4*)&hs[i*68 + j4*4] = v;
    }
    for (int e = tid; e < 128*256; e += 512) {
        int c = e >> 8, i = e & 255;
        ws[c*257 + i] = Wi[e];
    }
    __syncthreads();

    const int o2 = tid & 63;
    const int q  = tid >> 6;          // 0..7
    const int jb = q * 8;
    const int jv = jb >> 2;

    u64 acc[2][4];
#pragma unroll
    for (int a = 0; a < 2; a++)
#pragma unroll
        for (int k = 0; k < 4; k++) acc[a][k] = 0ull;

    const float* wA = ws + o2 * 257;
    const float* wB = ws + (o2 + 64) * 257;
    const ulonglong2* p = (const ulonglong2*)hs + jv;
#pragma unroll 4
    for (int i = 0; i < 256; i++) {
        u64 a = pk2s(wA[i]);
        u64 c = pk2s(wB[i]);
        ulonglong2 C0 = p[0], C1 = p[1];
        acc[0][0] = f2fma(a, C0.x, acc[0][0]);
        acc[0][1] = f2fma(a, C0.y, acc[0][1]);
        acc[0][2] = f2fma(a, C1.x, acc[0][2]);
        acc[0][3] = f2fma(a, C1.y, acc[0][3]);
        acc[1][0] = f2fma(c, C0.x, acc[1][0]);
        acc[1][1] = f2fma(c, C0.y, acc[1][1]);
        acc[1][2] = f2fma(c, C1.x, acc[1][2]);
        acc[1][3] = f2fma(c, C1.y, acc[1][3]);
        p += 17;
    }

    float* rb = g_res0 + (size_t)b * T0 * HID;
    const float biv[2] = { bi[o2], bi[o2 + 64] };
#pragma unroll
    for (int oo = 0; oo < 2; oo++) {
        int o = o2 + 64*oo;
#pragma unroll
        for (int k = 0; k < 4; k++) {
            int t = t0 + jb + 2*k;
            float2 x = upk(acc[oo][k]);
            rb[(size_t)t * HID + o]       = x.x + biv[oo];
            rb[(size_t)(t+1) * HID + o]   = x.y + biv[oo];
        }
    }
}

// =====================================================================
// Layer kernel: one dilated residual layer
// =====================================================================
__global__ __launch_bounds__(512, 1) void layer_kernel(
    int flip,
    const float* __restrict__ Wf, const float* __restrict__ bf,
    const float* __restrict__ Wg, const float* __restrict__ bg,
    const float* __restrict__ Wr, const float* __restrict__ br,
    int d, int Tnew, int off, int first)
{
    const float* src = flip ? g_res1 : g_res0;
    float*       dst = flip ? g_res0 : g_res1;

    extern __shared__ float sm[];
    float* s0   = sm;                 // [128][68]  res[t] tile, later out tile
    float* s1   = sm + 128*68;        // [128][68]  res[t+d] tile
    float* wbuf = sm + 2*128*68;      // 4 planes [128][65], later Wr [128][129]

    const int tid = threadIdx.x;
    const int b  = blockIdx.y;
    const int t0 = blockIdx.x * 64;
    const int Tk = Tnew + d;
    const float* sb = src + (size_t)b * T0 * HID;

    // load res tiles (transposed into [ch][time])
    for (int e = tid; e < 64*32; e += 512) {
        int j = e >> 5, i4 = e & 31;
        int t = t0 + j;
        float4 v0 = make_float4(0.f,0.f,0.f,0.f), v1 = v0;
        if (t < Tk)   v0 = *(const float4*)(sb + (size_t)t * HID + i4*4);
        if (t < Tnew) v1 = *(const float4*)(sb + (size_t)(t + d) * HID + i4*4);
        int r = i4 * 4;
        s0[(r+0)*68+j] = v0.x; s0[(r+1)*68+j] = v0.y; s0[(r+2)*68+j] = v0.z; s0[(r+3)*68+j] = v0.w;
        s1[(r+0)*68+j] = v1.x; s1[(r+1)*68+j] = v1.y; s1[(r+2)*68+j] = v1.z; s1[(r+3)*68+j] = v1.w;
    }

    const int o2  = tid & 63;
    const int q   = tid >> 6;       // 0..7
    const int mat = q >> 2;         // 0 = f, 1 = g
    const int jb  = (q & 3) * 16;
    const int jv  = jb >> 2;

    u64 acc[2][8];
#pragma unroll
    for (int a = 0; a < 2; a++)
#pragma unroll
        for (int k = 0; k < 8; k++) acc[a][k] = 0ull;

    // ---- GEMM1: pre_f / pre_g over 2 taps, 2 chunks of 64 i ----
    for (int c0 = 0; c0 < 128; c0 += 64) {
        if (c0) __syncthreads();
        for (int e = tid; e < 4*128*64; e += 512) {
            int plane = e >> 13, rem = e & 8191;
            int o = rem >> 6, ic = rem & 63;
            const float* W = (plane >> 1) ? Wg : Wf;
            wbuf[plane*8320 + o*65 + ic] = W[(size_t)((o << 7) + c0 + ic) * 2 + (plane & 1)];
        }
        __syncthreads();

        const float* w0a = wbuf + (mat*2    )*8320 + o2*65;
        const float* w1a = wbuf + (mat*2 + 1)*8320 + o2*65;
        const float* w0b = w0a + 64*65;
        const float* w1b = w1a + 64*65;
        const ulonglong2* p0 = (const ulonglong2*)s0 + (size_t)c0*17 + jv;
        const ulonglong2* p1 = (const ulonglong2*)s1 + (size_t)c0*17 + jv;

#pragma unroll 4
        for (int ic = 0; ic < 64; ic++) {
            u64 wa0 = pk2s(w0a[ic]);
            u64 wa1 = pk2s(w1a[ic]);
            u64 wc0 = pk2s(w0b[ic]);
            u64 wc1 = pk2s(w1b[ic]);
            ulonglong2 Av[4], Bv[4];
#pragma unroll
            for (int kk = 0; kk < 4; kk++) { Av[kk] = p0[kk]; Bv[kk] = p1[kk]; }
#pragma unroll
            for (int kk = 0; kk < 4; kk++) {
                acc[0][2*kk  ] = f2fma(wa0, Av[kk].x, acc[0][2*kk  ]);
                acc[0][2*kk+1] = f2fma(wa0, Av[kk].y, acc[0][2*kk+1]);
                acc[0][2*kk  ] = f2fma(wa1, Bv[kk].x, acc[0][2*kk  ]);
                acc[0][2*kk+1] = f2fma(wa1, Bv[kk].y, acc[0][2*kk+1]);
                acc[1][2*kk  ] = f2fma(wc0, Av[kk].x, acc[1][2*kk  ]);
                acc[1][2*kk+1] = f2fma(wc0, Av[kk].y, acc[1][2*kk+1]);
                acc[1][2*kk  ] = f2fma(wc1, Bv[kk].x, acc[1][2*kk  ]);
                acc[1][2*kk+1] = f2fma(wc1, Bv[kk].y, acc[1][2*kk+1]);
            }
            p0 += 17; p1 += 17;
        }
    }
    __syncthreads();

    // ---- activations: out = tanh(pre_f + bf) * sigmoid(pre_g + bg), into s0 ----
    const int oA = o2, oB = o2 + 64;
    if (mat == 1) {
        const float bv[2] = { bg[oA], bg[oB] };
#pragma unroll
        for (int oo = 0; oo < 2; oo++) {
            int o = o2 + 64*oo;
#pragma unroll
            for (int k = 0; k < 8; k++) {
                float2 v = upk(acc[oo][k]);
                float g0 = 1.f / (1.f + expf(-(v.x + bv[oo])));
                float g1 = 1.f / (1.f + expf(-(v.y + bv[oo])));
                s0[o*68 + jb + 2*k    ] = g0;
                s0[o*68 + jb + 2*k + 1] = g1;
            }
        }
    }
    __syncthreads();
    if (mat == 0) {
        const float bv[2] = { bf[oA], bf[oB] };
#pragma unroll
        for (int oo = 0; oo < 2; oo++) {
            int o = o2 + 64*oo;
#pragma unroll
            for (int k = 0; k < 8; k++) {
                float2 v = upk(acc[oo][k]);
                float f0 = tanhf(v.x + bv[oo]);
                float f1 = tanhf(v.y + bv[oo]);
                int idx = o*68 + jb + 2*k;
                s0[idx]     = f0 * s0[idx];
                s0[idx + 1] = f1 * s0[idx + 1];
            }
        }
    }
    __syncthreads();

    // ---- GEMM2: x = Wr . out ----
    for (int e = tid; e < 128*128; e += 512) {
        int o = e >> 7, i = e & 127;
        wbuf[o*129 + i] = Wr[(o << 7) + i];
    }
    __syncthreads();

    const int jb2 = q * 8;
    const int jv2 = jb2 >> 2;
    u64 acc2[2][4];
#pragma unroll
    for (int a = 0; a < 2; a++)
#pragma unroll
        for (int k = 0; k < 4; k++) acc2[a][k] = 0ull;

    const float* wrA = wbuf + o2 * 129;
    const float* wrB = wbuf + (o2 + 64) * 129;
    const ulonglong2* po = (const ulonglong2*)s0 + jv2;
#pragma unroll 4
    for (int i = 0; i < 128; i++) {
        u64 wA = pk2s(wrA[i]);
        u64 wB = pk2s(wrB[i]);
        ulonglong2 C0 = po[0], C1 = po[1];
        acc2[0][0] = f2fma(wA, C0.x, acc2[0][0]);
        acc2[0][1] = f2fma(wA, C0.y, acc2[0][1]);
        acc2[0][2] = f2fma(wA, C1.x, acc2[0][2]);
        acc2[0][3] = f2fma(wA, C1.y, acc2[0][3]);
        acc2[1][0] = f2fma(wB, C0.x, acc2[1][0]);
        acc2[1][1] = f2fma(wB, C0.y, acc2[1][1]);
        acc2[1][2] = f2fma(wB, C1.x, acc2[1][2]);
        acc2[1][3] = f2fma(wB, C1.y, acc2[1][3]);
        po += 17;
    }

    // ---- epilogue: residual + skip ----
    float* db  = dst + (size_t)b * T0 * HID;
    float* skb = g_skip + (size_t)b * TARGET * HID;
    const u64* s1q = (const u64*)s1;
    const float brv[2] = { br[oA], br[oB] };
#pragma unroll
    for (int oo = 0; oo < 2; oo++) {
        int o = o2 + 64*oo;
#pragma unroll
        for (int k = 0; k < 4; k++) {
            int j = jb2 + 2*k;
            float2 x = upk(acc2[oo][k]);
            float2 r = upk(s1q[o*34 + (jb2 >> 1) + k]);
            int t = t0 + j;
            if (t < Tnew) {
                float xv = x.x + brv[oo];
                db[(size_t)t * HID + o] = xv + r.x;
                int ts = t - off;
                if (ts >= 0) {
                    size_t si = (size_t)ts * HID + o;
                    if (first) skb[si] = xv; else skb[si] += xv;
                }
            }
            if (t + 1 < Tnew) {
                float xv = x.y + brv[oo];
                db[(size_t)(t+1) * HID + o] = xv + r.y;
                int ts = t + 1 - off;
                if (ts >= 0) {
                    size_t si = (size_t)ts * HID + o;
                    if (first) skb[si] = xv; else skb[si] += xv;
                }
            }
        }
    }
}

// =====================================================================
// Head 1: mid = relu(W1 . relu(skip) + b1)
// =====================================================================
__global__ __launch_bounds__(512, 1) void head1_kernel(
    const float* __restrict__ W1, const float* __restrict__ b1)
{
    extern __shared__ float sm[];
    float* hs = sm;              // [128][68]
    float* ws = sm + 128*68;     // [128][129]
    const int tid = threadIdx.x;
    const int b = blockIdx.y;
    const int t0 = blockIdx.x * 64;

    const float* skb = g_skip + (size_t)b * TARGET * HID;
    for (int e = tid; e < 64*32; e += 512) {
        int j = e >> 5, i4 = e & 31;
        int t = t0 + j;
        float4 v = make_float4(0.f,0.f,0.f,0.f);
        if (t < TARGET) v = *(const float4*)(skb + (size_t)t * HID + i4*4);
        int r = i4 * 4;
        hs[(r+0)*68+j] = fmaxf(v.x, 0.f);
        hs[(r+1)*68+j] = fmaxf(v.y, 0.f);
        hs[(r+2)*68+j] = fmaxf(v.z, 0.f);
        hs[(r+3)*68+j] = fmaxf(v.w, 0.f);
    }

    const int o2 = tid & 63;
    const int q  = tid >> 6;
    const int jb = q * 8;
    const int jv = jb >> 2;
    float* mb = g_mid + (size_t)b * TARGET * 512;

    for (int oc = 0; oc < 4; oc++) {
        __syncthreads();
        for (int e = tid; e < 128*128; e += 512) {
            int o = e >> 7, i = e & 127;
            ws[o*129 + i] = W1[(size_t)(oc*128 + o) * 128 + i];
        }
        __syncthreads();

        u64 acc[2][4];
#pragma unroll
        for (int a = 0; a < 2; a++)
#pragma unroll
            for (int k = 0; k < 4; k++) acc[a][k] = 0ull;

        const float* wA = ws + o2 * 129;
        const float* wB = ws + (o2 + 64) * 129;
        const ulonglong2* p = (const ulonglong2*)hs + jv;
#pragma unroll 4
        for (int i = 0; i < 128; i++) {
            u64 a = pk2s(wA[i]);
            u64 c = pk2s(wB[i]);
            ulonglong2 C0 = p[0], C1 = p[1];
            acc[0][0] = f2fma(a, C0.x, acc[0][0]);
            acc[0][1] = f2fma(a, C0.y, acc[0][1]);
            acc[0][2] = f2fma(a, C1.x, acc[0][2]);
            acc[0][3] = f2fma(a, C1.y, acc[0][3]);
            acc[1][0] = f2fma(c, C0.x, acc[1][0]);
            acc[1][1] = f2fma(c, C0.y, acc[1][1]);
            acc[1][2] = f2fma(c, C1.x, acc[1][2]);
            acc[1][3] = f2fma(c, C1.y, acc[1][3]);
            p += 17;
        }

#pragma unroll
        for (int oo = 0; oo < 2; oo++) {
            int og = oc*128 + o2 + 64*oo;
            float bv = b1[og];
#pragma unroll
            for (int k = 0; k < 4; k++) {
                int j = jb + 2*k;
                float2 x = upk(acc[oo][k]);
                int t = t0 + j;
                if (t < TARGET)     mb[(size_t)t * 512 + og]     = fmaxf(x.x + bv, 0.f);
                if (t + 1 < TARGET) mb[(size_t)(t+1) * 512 + og] = fmaxf(x.y + bv, 0.f);
            }
        }
    }
}

// =====================================================================
// Head 2: out = W2 . mid + b2, written as [(b*TARGET+t)][256]
// =====================================================================
__global__ __launch_bounds__(512, 1) void head2_kernel(
    const float* __restrict__ W2, const float* __restrict__ b2,
    float* __restrict__ out)
{
    extern __shared__ float sm[];
    float* hs = sm;              // [128][68]
    float* ws = sm + 128*68;     // [256][129]
    const int tid = threadIdx.x;
    const int b = blockIdx.y;
    const int t0 = blockIdx.x * 64;

    const int o2 = tid & 127;
    const int q  = tid >> 7;          // 0..3
    const int jb = q * 16;
    const int jv = jb >> 2;

    u64 acc[2][8];
#pragma unroll
    for (int a = 0; a < 2; a++)
#pragma unroll
        for (int k = 0; k < 8; k++) acc[a][k] = 0ull;

    const float* mb = g_mid + (size_t)b * TARGET * 512;

    for (int ic0 = 0; ic0 < 512; ic0 += 128) {
        if (ic0) __syncthreads();
        for (int e = tid; e < 64*32; e += 512) {
            int j = e >> 5, i4 = e & 31;
            int t = t0 + j;
            float4 v = make_float4(0.f,0.f,0.f,0.f);
            if (t < TARGET) v = *(const float4*)(mb + (size_t)t * 512 + ic0 + i4*4);
            int r = i4 * 4;
            hs[(r+0)*68+j] = v.x; hs[(r+1)*68+j] = v.y;
            hs[(r+2)*68+j] = v.z; hs[(r+3)*68+j] = v.w;
        }
        for (int e = tid; e < 256*128; e += 512) {
            int o = e >> 7, i = e & 127;
            ws[o*129 + i] = W2[(size_t)o * 512 + ic0 + i];
        }
        __syncthreads();

        const float* wA = ws + o2 * 129;
        const float* wB = ws + (o2 + 128) * 129;
        const ulonglong2* p = (const ulonglong2*)hs + jv;
#pragma unroll 4
        for (int i = 0; i < 128; i++) {
            u64 a = pk2s(wA[i]);
            u64 c = pk2s(wB[i]);
            ulonglong2 C0 = p[0], C1 = p[1], C2 = p[2], C3 = p[3];
            acc[0][0] = f2fma(a, C0.x, acc[0][0]);
            acc[0][1] = f2fma(a, C0.y, acc[0][1]);
            acc[0][2] = f2fma(a, C1.x, acc[0][2]);
            acc[0][3] = f2fma(a, C1.y, acc[0][3]);
            acc[0][4] = f2fma(a, C2.x, acc[0][4]);
            acc[0][5] = f2fma(a, C2.y, acc[0][5]);
            acc[0][6] = f2fma(a, C3.x, acc[0][6]);
            acc[0][7] = f2fma(a, C3.y, acc[0][7]);
            acc[1][0] = f2fma(c, C0.x, acc[1][0]);
            acc[1][1] = f2fma(c, C0.y, acc[1][1]);
            acc[1][2] = f2fma(c, C1.x, acc[1][2]);
            acc[1][3] = f2fma(c, C1.y, acc[1][3]);
            acc[1][4] = f2fma(c, C2.x, acc[1][4]);
            acc[1][5] = f2fma(c, C2.y, acc[1][5]);
            acc[1][6] = f2fma(c, C3.x, acc[1][6]);
            acc[1][7] = f2fma(c, C3.y, acc[1][7]);
            p += 17;
        }
    }

#pragma unroll
    for (int oo = 0; oo < 2; oo++) {
        int o = o2 + 128*oo;
        float bv = b2[o];
#pragma unroll
        for (int k = 0; k < 8; k++) {
            int j = jb + 2*k;
            float2 x = upk(acc[oo][k]);
            int t = t0 + j;
            if (t < TARGET)     out[((size_t)b * TARGET + t) * 256 + o]     = x.x + bv;
            if (t + 1 < TARGET) out[((size_t)b * TARGET + t + 1) * 256 + o] = x.y + bv;
        }
    }
}

// =====================================================================
// Host launcher
// =====================================================================
extern "C" void kernel_launch(void* const* d_in, const int* in_sizes, int n_in,
                              void* d_out, int out_size)
{
    (void)in_sizes; (void)n_in; (void)out_size;
    const float* inp = (const float*)d_in[0];
    const float* Wi  = (const float*)d_in[1];
    const float* bi  = (const float*)d_in[2];
    const float* Wf  = (const float*)d_in[3];
    const float* bf  = (const float*)d_in[4];
    const float* Wg  = (const float*)d_in[5];
    const float* bg  = (const float*)d_in[6];
    const float* Wr  = (const float*)d_in[7];
    const float* br  = (const float*)d_in[8];
    const float* W1  = (const float*)d_in[9];
    const float* b1  = (const float*)d_in[10];
    const float* W2  = (const float*)d_in[11];
    const float* b2  = (const float*)d_in[12];
    float* out = (float*)d_out;

    cudaFuncSetAttribute(in_kernel,    cudaFuncAttributeMaxDynamicSharedMemorySize, IN_SMEM);
    cudaFuncSetAttribute(layer_kernel, cudaFuncAttributeMaxDynamicSharedMemorySize, LAYER_SMEM);
    cudaFuncSetAttribute(head1_kernel, cudaFuncAttributeMaxDynamicSharedMemorySize, H1_SMEM);
    cudaFuncSetAttribute(head2_kernel, cudaFuncAttributeMaxDynamicSharedMemorySize, H2_SMEM);

    in_kernel<<<dim3(T0/64, NB), 512, IN_SMEM>>>(inp, Wi, bi);

    static const int dil[NLAY] = {1,2,4,8,16,32,64,128,256,512,
                                  1,2,4,8,16,32,64,128,256,512};
    int Tcur = T0;
    int flip = 0;
    for (int l = 0; l < NLAY; l++) {
        int d = dil[l];
        int Tnew = Tcur - d;
        int off = Tnew - TARGET;
        dim3 g((Tnew + 63) / 64, NB);
        layer_kernel<<<g, 512, LAYER_SMEM>>>(flip,
            Wf + (size_t)l * 128 * 128 * 2, bf + l * 128,
            Wg + (size_t)l * 128 * 128 * 2, bg + l * 128,
            Wr + (size_t)l * 128 * 128,     br + l * 128,
            d, Tnew, off, l == 0);
        flip ^= 1;
        Tcur = Tnew;
    }

    dim3 gh((TARGET + 63) / 64, NB);
    head1_kernel<<<gh, 512, H1_SMEM>>>(W1, b1);
    head2_kernel<<<gh, 512, H2_SMEM>>>(W2, b2, out);
}

// round 3
// speedup vs baseline: 3.1857x; 3.1857x over previous
#include <cuda_runtime.h>
#include <cuda_fp16.h>
#include <math.h>
#include <stdint.h>

typedef unsigned long long u64;
typedef unsigned int u32;

#define NB      8
#define T0      8192
#define HID     128
#define TARGET  6146
#define NLAY    20

// ---------------- scratch (device globals; no allocation) ----------------
__device__ float g_res0[(size_t)NB * T0 * HID];
__device__ float g_res1[(size_t)NB * T0 * HID];
__device__ float g_skip[(size_t)NB * TARGET * HID];
__device__ float g_mid [(size_t)NB * TARGET * 512];

// ---------------- packed f32x2 helpers (FFMA2 path, in/head) ----------------
__device__ __forceinline__ u64 pk2s(float w) {
    u64 r; asm("mov.b64 %0, {%1, %1};" : "=l"(r) : "f"(w)); return r;
}
__device__ __forceinline__ float2 upk(u64 v) {
    float2 f; asm("mov.b64 {%0, %1}, %2;" : "=f"(f.x), "=f"(f.y) : "l"(v)); return f;
}
__device__ __forceinline__ u64 f2fma(u64 a, u64 b, u64 c) {
    u64 d; asm("fma.rn.f32x2 %0, %1, %2, %3;" : "=l"(d) : "l"(a), "l"(b), "l"(c)); return d;
}

// ---------------- fp16 mma helpers ----------------
__device__ __forceinline__ u32 pkhalf2(float lo, float hi) {
    u32 u;
    asm("{ .reg .b16 l, h; cvt.rn.f16.f32 l, %1; cvt.rn.f16.f32 h, %2; mov.b32 %0, {l, h}; }"
        : "=r"(u) : "f"(lo), "f"(hi));
    return u;
}
__device__ __forceinline__ void mma16816(float* c, u32 a0, u32 a1, u32 a2, u32 a3,
                                         u32 b0, u32 b1) {
    asm volatile(
        "mma.sync.aligned.m16n8k16.row.col.f32.f16.f16.f32 "
        "{%0,%1,%2,%3}, {%4,%5,%6,%7}, {%8,%9}, {%0,%1,%2,%3};"
        : "+f"(c[0]), "+f"(c[1]), "+f"(c[2]), "+f"(c[3])
        : "r"(a0), "r"(a1), "r"(a2), "r"(a3), "r"(b0), "r"(b1));
}
__device__ __forceinline__ float fast_tanh(float x) {
    float y; asm("tanh.approx.f32 %0, %1;" : "=f"(y) : "f"(x)); return y;
}
__device__ __forceinline__ float fast_sig(float x) {
    float e;
    asm("ex2.approx.f32 %0, %1;" : "=f"(e) : "f"(-x * 1.4426950408889634f));
    float r;
    asm("rcp.approx.f32 %0, %1;" : "=f"(r) : "f"(1.0f + e));
    return r;
}

// smem byte map for layer_mma
// SM_ACT: s_act half[64][264] (taps interleaved k=2i+tap); later s_gate f32[64][132]; later s_x f32[64][132]
// SM_OUT: s_out half[64][264] (GEMM2 B operand, k=ch)
// SM_W:   GEMM1 chunks: f [128][40]half (10240) + g (10240); GEMM2 chunk [128][72]half (18432)
#define SM_ACT  0
#define SM_OUT  33792
#define SM_W    67584
#define LMM_SMEM (SM_W + 20480)   // 88064

// =====================================================================
// Layer kernel: one dilated residual layer via fp16 mma.sync (HMMA)
// =====================================================================
__global__ __launch_bounds__(256, 2) void layer_mma(
    int flip,
    const float* __restrict__ Wf, const float* __restrict__ bf,
    const float* __restrict__ Wg, const float* __restrict__ bg,
    const float* __restrict__ Wr, const float* __restrict__ br,
    int d, int Tnew, int off, int first)
{
    extern __shared__ char sm[];
    u32* smu = (u32*)sm;

    const int tid = threadIdx.x, wid = tid >> 5, lane = tid & 31;
    const int g8 = lane >> 2, tig = lane & 3;
    const int b = blockIdx.y, t0 = blockIdx.x * 64;
    const int Tcur = Tnew + d;
    const float* srcb = (flip ? g_res1 : g_res0) + (size_t)b * T0 * HID;
    float*       dstb = (flip ? g_res0 : g_res1) + (size_t)b * T0 * HID;
    float*       skb  = g_skip + (size_t)b * TARGET * HID;

    // ---- stage activations, taps interleaved: s_act[t][k=2c+tap] ----
    for (int e = tid; e < 64 * 32; e += 256) {
        int j = e >> 5, c4 = e & 31;
        int ta = t0 + j;     if (ta > Tcur - 1) ta = Tcur - 1;
        int tb = t0 + j + d; if (tb > Tcur - 1) tb = Tcur - 1;
        float4 A = *(const float4*)(srcb + (size_t)ta * HID + c4 * 4);
        float4 B = *(const float4*)(srcb + (size_t)tb * HID + c4 * 4);
        uint4 st;
        st.x = pkhalf2(A.x, B.x);
        st.y = pkhalf2(A.y, B.y);
        st.z = pkhalf2(A.z, B.z);
        st.w = pkhalf2(A.w, B.w);
        *(uint4*)(sm + SM_ACT + j * 528 + c4 * 16) = st;
    }

    const int chb = (wid & 3) * 32;
    float acc[16][4];
#pragma unroll
    for (int i = 0; i < 16; i++)
#pragma unroll
        for (int k = 0; k < 4; k++) acc[i][k] = 0.f;

    // ---- GEMM1: f (warps 0-3) / g (warps 4-7), K=256 halves, 8 chunks ----
    const u32 awb = (u32)((SM_W + ((wid < 4) ? 0 : 10240)) >> 2);
    for (int kc = 0; kc < 8; kc++) {
        __syncthreads();
        for (int e = tid; e < 2048; e += 256) {
            int m = e >> 10;
            int r = e & 1023, o = r >> 3, q = r & 7;
            const float* W = m ? Wg : Wf;
            float4 v = *(const float4*)(W + (size_t)o * 256 + kc * 32 + q * 4);
            *(uint2*)(sm + SM_W + m * 10240 + o * 80 + q * 8) =
                make_uint2(pkhalf2(v.x, v.y), pkhalf2(v.z, v.w));
        }
        __syncthreads();
#pragma unroll
        for (int ks = 0; ks < 2; ks++) {
            u32 a[2][4];
#pragma unroll
            for (int mt = 0; mt < 2; mt++) {
                u32 w0 = awb + (u32)((chb + mt * 16 + g8) * 20 + ks * 8 + tig);
                a[mt][0] = smu[w0];
                a[mt][1] = smu[w0 + 8 * 20];
                a[mt][2] = smu[w0 + 4];
                a[mt][3] = smu[w0 + 8 * 20 + 4];
            }
#pragma unroll
            for (int nt = 0; nt < 8; nt++) {
                u32 bw = (u32)((nt * 8 + g8) * 132 + kc * 16 + ks * 8 + tig);
                u32 b0 = smu[bw], b1 = smu[bw + 4];
                mma16816(acc[nt],     a[0][0], a[0][1], a[0][2], a[0][3], b0, b1);
                mma16816(acc[8 + nt], a[1][0], a[1][1], a[1][2], a[1][3], b0, b1);
            }
        }
    }

    // ---- epilogue1: gate then product ----
    __syncthreads();
    float* sgate = (float*)(sm + SM_ACT);
    if (wid >= 4) {
        float bg0 = bg[chb + g8],      bg8  = bg[chb + g8 + 8];
        float bg16 = bg[chb + 16 + g8], bg24 = bg[chb + 24 + g8];
#pragma unroll
        for (int mt = 0; mt < 2; mt++) {
            int ch0 = chb + mt * 16 + g8;
            float bv0 = mt ? bg16 : bg0;
            float bv8 = mt ? bg24 : bg8;
#pragma unroll
            for (int nt = 0; nt < 8; nt++) {
                int t_ = nt * 8 + 2 * tig;
                float* a4 = acc[mt * 8 + nt];
                sgate[(t_    ) * 132 + ch0    ] = fast_sig(a4[0] + bv0);
                sgate[(t_ + 1) * 132 + ch0    ] = fast_sig(a4[1] + bv0);
                sgate[(t_    ) * 132 + ch0 + 8] = fast_sig(a4[2] + bv8);
                sgate[(t_ + 1) * 132 + ch0 + 8] = fast_sig(a4[3] + bv8);
            }
        }
    }
    __syncthreads();
    if (wid < 4) {
        __half* sout = (__half*)(sm + SM_OUT);
        float bf0 = bf[chb + g8],      bf8  = bf[chb + g8 + 8];
        float bf16 = bf[chb + 16 + g8], bf24 = bf[chb + 24 + g8];
#pragma unroll
        for (int mt = 0; mt < 2; mt++) {
            int ch0 = chb + mt * 16 + g8;
            float bv0 = mt ? bf16 : bf0;
            float bv8 = mt ? bf24 : bf8;
#pragma unroll
            for (int nt = 0; nt < 8; nt++) {
                int t_ = nt * 8 + 2 * tig;
                float* a4 = acc[mt * 8 + nt];
                float p0 = fast_tanh(a4[0] + bv0) * sgate[(t_    ) * 132 + ch0    ];
                float p1 = fast_tanh(a4[1] + bv0) * sgate[(t_ + 1) * 132 + ch0    ];
                float p2 = fast_tanh(a4[2] + bv8) * sgate[(t_    ) * 132 + ch0 + 8];
                float p3 = fast_tanh(a4[3] + bv8) * sgate[(t_ + 1) * 132 + ch0 + 8];
                sout[(t_    ) * 264 + ch0    ] = __float2half_rn(p0);
                sout[(t_ + 1) * 264 + ch0    ] = __float2half_rn(p1);
                sout[(t_    ) * 264 + ch0 + 8] = __float2half_rn(p2);
                sout[(t_ + 1) * 264 + ch0 + 8] = __float2half_rn(p3);
            }
        }
    }

    // ---- GEMM2: x = Wr . out, K=128 halves, 2 chunks of 64 ----
#pragma unroll
    for (int i = 0; i < 8; i++)
#pragma unroll
        for (int k = 0; k < 4; k++) acc[i][k] = 0.f;

    const int nb2 = (wid >> 2) * 32;
    for (int kc = 0; kc < 2; kc++) {
        __syncthreads();
        for (int e = tid; e < 2048; e += 256) {
            int o = e >> 4, q = e & 15;
            float4 v = *(const float4*)(Wr + (size_t)o * 128 + kc * 64 + q * 4);
            *(uint2*)(sm + SM_W + o * 144 + q * 8) =
                make_uint2(pkhalf2(v.x, v.y), pkhalf2(v.z, v.w));
        }
        __syncthreads();
#pragma unroll
        for (int ks = 0; ks < 4; ks++) {
            u32 a[2][4];
#pragma unroll
            for (int mt = 0; mt < 2; mt++) {
                u32 w0 = (u32)((SM_W >> 2) + (chb + mt * 16 + g8) * 36 + ks * 8 + tig);
                a[mt][0] = smu[w0];
                a[mt][1] = smu[w0 + 8 * 36];
                a[mt][2] = smu[w0 + 4];
                a[mt][3] = smu[w0 + 8 * 36 + 4];
            }
#pragma unroll
            for (int nt = 0; nt < 4; nt++) {
                u32 bw = (u32)((SM_OUT >> 2) + (nb2 + nt * 8 + g8) * 132 + kc * 32 + ks * 8 + tig);
                u32 b0 = smu[bw], b1 = smu[bw + 4];
                mma16816(acc[nt],     a[0][0], a[0][1], a[0][2], a[0][3], b0, b1);
                mma16816(acc[4 + nt], a[1][0], a[1][1], a[1][2], a[1][3], b0, b1);
            }
        }
    }

    // ---- epilogue2: x + br -> s_x; then residual + skip (vectorized) ----
    __syncthreads();
    float* sx = (float*)(sm + SM_ACT);
    {
        float br0 = br[chb + g8],      br8  = br[chb + g8 + 8];
        float br16 = br[chb + 16 + g8], br24 = br[chb + 24 + g8];
#pragma unroll
        for (int mt = 0; mt < 2; mt++) {
            int ch0 = chb + mt * 16 + g8;
            float bv0 = mt ? br16 : br0;
            float bv8 = mt ? br24 : br8;
#pragma unroll
            for (int nt = 0; nt < 4; nt++) {
                int t_ = nb2 + nt * 8 + 2 * tig;
                float* a4 = acc[mt * 4 + nt];
                sx[(t_    ) * 132 + ch0    ] = a4[0] + bv0;
                sx[(t_ + 1) * 132 + ch0    ] = a4[1] + bv0;
                sx[(t_    ) * 132 + ch0 + 8] = a4[2] + bv8;
                sx[(t_ + 1) * 132 + ch0 + 8] = a4[3] + bv8;
            }
        }
    }
    __syncthreads();
    for (int e = tid; e < 64 * 32; e += 256) {
        int j = e >> 5, c4 = e & 31;
        int t = t0 + j;
        if (t < Tnew) {
            float4 x = *(float4*)(sx + j * 132 + c4 * 4);
            float4 r = *(const float4*)(srcb + (size_t)(t + d) * HID + c4 * 4);
            float4 o;
            o.x = x.x + r.x; o.y = x.y + r.y; o.z = x.z + r.z; o.w = x.w + r.w;
            *(float4*)(dstb + (size_t)t * HID + c4 * 4) = o;
            int ts = t - off;
            if (ts >= 0) {
                float* sp = skb + (size_t)ts * HID + c4 * 4;
                if (first) {
                    *(float4*)sp = x;
                } else {
                    float4 s = *(float4*)sp;
                    s.x += x.x; s.y += x.y; s.z += x.z; s.w += x.w;
                    *(float4*)sp = s;
                }
            }
        }
    }
}

// smem sizes (bytes) for FFMA2 kernels
#define IN_SMEM    ((256*68 + 128*257) * 4)
#define H1_SMEM    ((128*68 + 128*129) * 4)
#define H2_SMEM    ((128*68 + 256*129) * 4)

// =====================================================================
// Input GEMM: res0[b][t][c] = Wi[c,:] . inputs[b,:,t] + bi[c]
// =====================================================================
__global__ __launch_bounds__(512, 1) void in_kernel(
    const float* __restrict__ inp, const float* __restrict__ Wi,
    const float* __restrict__ bi)
{
    extern __shared__ float smf[];
    float* hs = smf;             // [256][68]
    float* ws = smf + 256*68;    // [128][257]
    const int tid = threadIdx.x;
    const int b = blockIdx.y;
    const int t0 = blockIdx.x * 64;

    const float* ib = inp + (size_t)b * 256 * T0;
    for (int e = tid; e < 256*16; e += 512) {
        int i = e >> 4, j4 = e & 15;
        float4 v = *(const float4*)(ib + (size_t)i * T0 + t0 + j4*4);
        *(float4*)&hs[i*68 + j4*4] = v;
    }
    for (int e = tid; e < 128*256; e += 512) {
        int c = e >> 8, i = e & 255;
        ws[c*257 + i] = Wi[e];
    }
    __syncthreads();

    const int o2 = tid & 63;
    const int q  = tid >> 6;
    const int jb = q * 8;
    const int jv = jb >> 2;

    u64 acc[2][4];
#pragma unroll
    for (int a = 0; a < 2; a++)
#pragma unroll
        for (int k = 0; k < 4; k++) acc[a][k] = 0ull;

    const float* wA = ws + o2 * 257;
    const float* wB = ws + (o2 + 64) * 257;
    const ulonglong2* p = (const ulonglong2*)hs + jv;
#pragma unroll 4
    for (int i = 0; i < 256; i++) {
        u64 a = pk2s(wA[i]);
        u64 c = pk2s(wB[i]);
        ulonglong2 C0 = p[0], C1 = p[1];
        acc[0][0] = f2fma(a, C0.x, acc[0][0]);
        acc[0][1] = f2fma(a, C0.y, acc[0][1]);
        acc[0][2] = f2fma(a, C1.x, acc[0][2]);
        acc[0][3] = f2fma(a, C1.y, acc[0][3]);
        acc[1][0] = f2fma(c, C0.x, acc[1][0]);
        acc[1][1] = f2fma(c, C0.y, acc[1][1]);
        acc[1][2] = f2fma(c, C1.x, acc[1][2]);
        acc[1][3] = f2fma(c, C1.y, acc[1][3]);
        p += 17;
    }

    float* rb = g_res0 + (size_t)b * T0 * HID;
    const float biv[2] = { bi[o2], bi[o2 + 64] };
#pragma unroll
    for (int oo = 0; oo < 2; oo++) {
        int o = o2 + 64*oo;
#pragma unroll
        for (int k = 0; k < 4; k++) {
            int t = t0 + jb + 2*k;
            float2 x = upk(acc[oo][k]);
            rb[(size_t)t * HID + o]       = x.x + biv[oo];
            rb[(size_t)(t+1) * HID + o]   = x.y + biv[oo];
        }
    }
}

// =====================================================================
// Head 1: mid = relu(W1 . relu(skip) + b1)
// =====================================================================
__global__ __launch_bounds__(512, 1) void head1_kernel(
    const float* __restrict__ W1, const float* __restrict__ b1)
{
    extern __shared__ float smf[];
    float* hs = smf;              // [128][68]
    float* ws = smf + 128*68;     // [128][129]
    const int tid = threadIdx.x;
    const int b = blockIdx.y;
    const int t0 = blockIdx.x * 64;

    const float* skb = g_skip + (size_t)b * TARGET * HID;
    for (int e = tid; e < 64*32; e += 512) {
        int j = e >> 5, i4 = e & 31;
        int t = t0 + j;
        float4 v = make_float4(0.f,0.f,0.f,0.f);
        if (t < TARGET) v = *(const float4*)(skb + (size_t)t * HID + i4*4);
        int r = i4 * 4;
        hs[(r+0)*68+j] = fmaxf(v.x, 0.f);
        hs[(r+1)*68+j] = fmaxf(v.y, 0.f);
        hs[(r+2)*68+j] = fmaxf(v.z, 0.f);
        hs[(r+3)*68+j] = fmaxf(v.w, 0.f);
    }

    const int o2 = tid & 63;
    const int q  = tid >> 6;
    const int jb = q * 8;
    const int jv = jb >> 2;
    float* mb = g_mid + (size_t)b * TARGET * 512;

    for (int oc = 0; oc < 4; oc++) {
        __syncthreads();
        for (int e = tid; e < 128*128; e += 512) {
            int o = e >> 7, i = e & 127;
            ws[o*129 + i] = W1[(size_t)(oc*128 + o) * 128 + i];
        }
        __syncthreads();

        u64 acc[2][4];
#pragma unroll
        for (int a = 0; a < 2; a++)
#pragma unroll
            for (int k = 0; k < 4; k++) acc[a][k] = 0ull;

        const float* wA = ws + o2 * 129;
        const float* wB = ws + (o2 + 64) * 129;
        const ulonglong2* p = (const ulonglong2*)hs + jv;
#pragma unroll 4
        for (int i = 0; i < 128; i++) {
            u64 a = pk2s(wA[i]);
            u64 c = pk2s(wB[i]);
            ulonglong2 C0 = p[0], C1 = p[1];
            acc[0][0] = f2fma(a, C0.x, acc[0][0]);
            acc[0][1] = f2fma(a, C0.y, acc[0][1]);
            acc[0][2] = f2fma(a, C1.x, acc[0][2]);
            acc[0][3] = f2fma(a, C1.y, acc[0][3]);
            acc[1][0] = f2fma(c, C0.x, acc[1][0]);
            acc[1][1] = f2fma(c, C0.y, acc[1][1]);
            acc[1][2] = f2fma(c, C1.x, acc[1][2]);
            acc[1][3] = f2fma(c, C1.y, acc[1][3]);
            p += 17;
        }

#pragma unroll
        for (int oo = 0; oo < 2; oo++) {
            int og = oc*128 + o2 + 64*oo;
            float bv = b1[og];
#pragma unroll
            for (int k = 0; k < 4; k++) {
                int j = jb + 2*k;
                float2 x = upk(acc[oo][k]);
                int t = t0 + j;
                if (t < TARGET)     mb[(size_t)t * 512 + og]     = fmaxf(x.x + bv, 0.f);
                if (t + 1 < TARGET) mb[(size_t)(t+1) * 512 + og] = fmaxf(x.y + bv, 0.f);
            }
        }
    }
}

// =====================================================================
// Head 2: out = W2 . mid + b2
// =====================================================================
__global__ __launch_bounds__(512, 1) void head2_kernel(
    const float* __restrict__ W2, const float* __restrict__ b2,
    float* __restrict__ out)
{
    extern __shared__ float smf[];
    float* hs = smf;              // [128][68]
    float* ws = smf + 128*68;     // [256][129]
    const int tid = threadIdx.x;
    const int b = blockIdx.y;
    const int t0 = blockIdx.x * 64;

    const int o2 = tid & 127;
    const int q  = tid >> 7;
    const int jb = q * 16;
    const int jv = jb >> 2;

    u64 acc[2][8];
#pragma unroll
    for (int a = 0; a < 2; a++)
#pragma unroll
        for (int k = 0; k < 8; k++) acc[a][k] = 0ull;

    const float* mb = g_mid + (size_t)b * TARGET * 512;

    for (int ic0 = 0; ic0 < 512; ic0 += 128) {
        if (ic0) __syncthreads();
        for (int e = tid; e < 64*32; e += 512) {
            int j = e >> 5, i4 = e & 31;
            int t = t0 + j;
            float4 v = make_float4(0.f,0.f,0.f,0.f);
            if (t < TARGET) v = *(const float4*)(mb + (size_t)t * 512 + ic0 + i4*4);
            int r = i4 * 4;
            hs[(r+0)*68+j] = v.x; hs[(r+1)*68+j] = v.y;
            hs[(r+2)*68+j] = v.z; hs[(r+3)*68+j] = v.w;
        }
        for (int e = tid; e < 256*128; e += 512) {
            int o = e >> 7, i = e & 127;
            ws[o*129 + i] = W2[(size_t)o * 512 + ic0 + i];
        }
        __syncthreads();

        const float* wA = ws + o2 * 129;
        const float* wB = ws + (o2 + 128) * 129;
        const ulonglong2* p = (const ulonglong2*)hs + jv;
#pragma unroll 4
        for (int i = 0; i < 128; i++) {
            u64 a = pk2s(wA[i]);
            u64 c = pk2s(wB[i]);
            ulonglong2 C0 = p[0], C1 = p[1], C2 = p[2], C3 = p[3];
            acc[0][0] = f2fma(a, C0.x, acc[0][0]);
            acc[0][1] = f2fma(a, C0.y, acc[0][1]);
            acc[0][2] = f2fma(a, C1.x, acc[0][2]);
            acc[0][3] = f2fma(a, C1.y, acc[0][3]);
            acc[0][4] = f2fma(a, C2.x, acc[0][4]);
            acc[0][5] = f2fma(a, C2.y, acc[0][5]);
            acc[0][6] = f2fma(a, C3.x, acc[0][6]);
            acc[0][7] = f2fma(a, C3.y, acc[0][7]);
            acc[1][0] = f2fma(c, C0.x, acc[1][0]);
            acc[1][1] = f2fma(c, C0.y, acc[1][1]);
            acc[1][2] = f2fma(c, C1.x, acc[1][2]);
            acc[1][3] = f2fma(c, C1.y, acc[1][3]);
            acc[1][4] = f2fma(c, C2.x, acc[1][4]);
            acc[1][5] = f2fma(c, C2.y, acc[1][5]);
            acc[1][6] = f2fma(c, C3.x, acc[1][6]);
            acc[1][7] = f2fma(c, C3.y, acc[1][7]);
            p += 17;
        }
    }

#pragma unroll
    for (int oo = 0; oo < 2; oo++) {
        int o = o2 + 128*oo;
        float bv = b2[o];
#pragma unroll
        for (int k = 0; k < 8; k++) {
            int j = jb + 2*k;
            float2 x = upk(acc[oo][k]);
            int t = t0 + j;
            if (t < TARGET)     out[((size_t)b * TARGET + t) * 256 + o]     = x.x + bv;
            if (t + 1 < TARGET) out[((size_t)b * TARGET + t + 1) * 256 + o] = x.y + bv;
        }
    }
}

// =====================================================================
// Host launcher
// =====================================================================
extern "C" void kernel_launch(void* const* d_in, const int* in_sizes, int n_in,
                              void* d_out, int out_size)
{
    (void)in_sizes; (void)n_in; (void)out_size;
    const float* inp = (const float*)d_in[0];
    const float* Wi  = (const float*)d_in[1];
    const float* bi  = (const float*)d_in[2];
    const float* Wf  = (const float*)d_in[3];
    const float* bf  = (const float*)d_in[4];
    const float* Wg  = (const float*)d_in[5];
    const float* bg  = (const float*)d_in[6];
    const float* Wr  = (const float*)d_in[7];
    const float* br  = (const float*)d_in[8];
    const float* W1  = (const float*)d_in[9];
    const float* b1  = (const float*)d_in[10];
    const float* W2  = (const float*)d_in[11];
    const float* b2  = (const float*)d_in[12];
    float* out = (float*)d_out;

    cudaFuncSetAttribute(in_kernel,    cudaFuncAttributeMaxDynamicSharedMemorySize, IN_SMEM);
    cudaFuncSetAttribute(layer_mma,    cudaFuncAttributeMaxDynamicSharedMemorySize, LMM_SMEM);
    cudaFuncSetAttribute(head1_kernel, cudaFuncAttributeMaxDynamicSharedMemorySize, H1_SMEM);
    cudaFuncSetAttribute(head2_kernel, cudaFuncAttributeMaxDynamicSharedMemorySize, H2_SMEM);

    in_kernel<<<dim3(T0/64, NB), 512, IN_SMEM>>>(inp, Wi, bi);

    static const int dil[NLAY] = {1,2,4,8,16,32,64,128,256,512,
                                  1,2,4,8,16,32,64,128,256,512};
    int Tcur = T0;
    int flip = 0;
    for (int l = 0; l < NLAY; l++) {
        int d = dil[l];
        int Tnew = Tcur - d;
        int off = Tnew - TARGET;
        dim3 g((Tnew + 63) / 64, NB);
        layer_mma<<<g, 256, LMM_SMEM>>>(flip,
            Wf + (size_t)l * 128 * 128 * 2, bf + l * 128,
            Wg + (size_t)l * 128 * 128 * 2, bg + l * 128,
            Wr + (size_t)l * 128 * 128,     br + l * 128,
            d, Tnew, off, l == 0);
        flip ^= 1;
        Tcur = Tnew;
    }

    dim3 gh((TARGET + 63) / 64, NB);
    head1_kernel<<<gh, 512, H1_SMEM>>>(W1, b1);
    head2_kernel<<<gh, 512, H2_SMEM>>>(W2, b2, out);
}